// round 3
// baseline (speedup 1.0000x reference)
#include <cuda_runtime.h>
#include <math.h>

// ---------------- problem constants ----------------
#define B_    8
#define L_    1024
#define DM_   256
#define DI_   512
#define DS_   16
#define DTR_  16
#define NL_   4
#define NT    (B_*L_)       // 8192 tokens
#define MH_   96

// ---------------- scratch (device globals; no allocation allowed) ----------------
__device__ float g_h   [NT*DM_];        // residual stream
__device__ float g_u   [NT*DM_];        // layernorm output
__device__ float g_xz  [NT*2*DI_];      // in_proj output (xc | z)
__device__ float g_xcs [NT*DI_];        // conv+silu output
__device__ float g_xd  [NT*48];         // xproj output
__device__ float g_dt  [NT*DI_];        // softplus(dt)
__device__ float g_Bm  [NT*DS_];
__device__ float g_Cm  [NT*DS_];
__device__ float g_ys  [NT*DI_];        // gated scan output
__device__ float g_stats[2*B_];         // mean,std per batch

// ---------------- per-batch mean / std (ddof=1) ----------------
__global__ void stats_kernel(const float* __restrict__ x, float* __restrict__ stats)
{
    __shared__ float sm[256];
    int b = blockIdx.x, tid = threadIdx.x;
    float s = 0.f;
    for (int l = tid; l < L_; l += 256) s += x[b*L_ + l];
    sm[tid] = s; __syncthreads();
    for (int o = 128; o > 0; o >>= 1) { if (tid < o) sm[tid] += sm[tid+o]; __syncthreads(); }
    float mean = sm[0] * (1.f/L_);
    __syncthreads();
    float s2 = 0.f;
    for (int l = tid; l < L_; l += 256) { float d = x[b*L_ + l] - mean; s2 += d*d; }
    sm[tid] = s2; __syncthreads();
    for (int o = 128; o > 0; o >>= 1) { if (tid < o) sm[tid] += sm[tid+o]; __syncthreads(); }
    if (tid == 0) {
        float st = sqrtf(sm[0] / (float)(L_-1));
        st = fmaxf(st, 1e-6f);
        stats[2*b] = mean; stats[2*b+1] = st;
    }
}

// ---------------- input embed + positional encoding ----------------
__global__ void embed_kernel(const float* __restrict__ x, const float* __restrict__ inp_w,
                             const float* __restrict__ inp_b, const float* __restrict__ stats,
                             float* __restrict__ h)
{
    int tok = blockIdx.x;
    int d   = threadIdx.x;
    int b = tok >> 10, l = tok & 1023;
    float xn = (x[tok] - stats[2*b]) / stats[2*b+1];
    float div = expf(-(float)(d & ~1) * (9.2103403719761836f / 256.f));   // ln(1e4)/DM
    float ang = (float)l * div;
    float pe  = (d & 1) ? cosf(ang) : sinf(ang);
    h[tok*DM_ + d] = xn * inp_w[d] + inp_b[d] + pe;
}

// ---------------- per-token layernorm (one warp / token) ----------------
__global__ void ln_kernel(const float* __restrict__ in,
                          const float* __restrict__ gw, const float* __restrict__ bw,
                          float* __restrict__ out)
{
    int gt   = blockIdx.x*blockDim.x + threadIdx.x;
    int tok  = gt >> 5;
    int lane = gt & 31;
    const float4* row = (const float4*)(in + tok*DM_);
    float4 v0 = row[lane];
    float4 v1 = row[lane+32];
    float s = v0.x+v0.y+v0.z+v0.w + v1.x+v1.y+v1.z+v1.w;
#pragma unroll
    for (int o = 16; o; o >>= 1) s += __shfl_xor_sync(0xffffffffu, s, o);
    float mean = s * (1.f/DM_);
    float d0=v0.x-mean, d1=v0.y-mean, d2=v0.z-mean, d3=v0.w-mean;
    float d4=v1.x-mean, d5=v1.y-mean, d6=v1.z-mean, d7=v1.w-mean;
    float q = d0*d0+d1*d1+d2*d2+d3*d3+d4*d4+d5*d5+d6*d6+d7*d7;
#pragma unroll
    for (int o = 16; o; o >>= 1) q += __shfl_xor_sync(0xffffffffu, q, o);
    float rstd = rsqrtf(q * (1.f/DM_) + 1e-5f);
    float4 g0=((const float4*)gw)[lane], g1=((const float4*)gw)[lane+32];
    float4 b0=((const float4*)bw)[lane], b1=((const float4*)bw)[lane+32];
    float4 o0, o1;
    o0.x=d0*rstd*g0.x+b0.x; o0.y=d1*rstd*g0.y+b0.y; o0.z=d2*rstd*g0.z+b0.z; o0.w=d3*rstd*g0.w+b0.w;
    o1.x=d4*rstd*g1.x+b1.x; o1.y=d5*rstd*g1.y+b1.y; o1.z=d6*rstd*g1.z+b1.z; o1.w=d7*rstd*g1.w+b1.w;
    ((float4*)(out + tok*DM_))[lane]    = o0;
    ((float4*)(out + tok*DM_))[lane+32] = o1;
}

// ---------------- generic fp32 GEMM:  C[M,N] (+)= A[M,K] * B[N,K]^T ----------------
// tiles: 128(M) x 64(N) x 16(K), 256 threads, 8x4 per thread
template<bool ADD>
__global__ void __launch_bounds__(256, 2) gemm_tn(
    const float* __restrict__ A, const float* __restrict__ Bw,
    float* __restrict__ C, int M, int N, int K)
{
    __shared__ float As[16][128];
    __shared__ float Bs[16][64];
    const int tid = threadIdx.x;
    const int m0 = blockIdx.y * 128;
    const int n0 = blockIdx.x * 64;
    const int tx = tid & 15;
    const int ty = tid >> 4;
    float acc[8][4];
#pragma unroll
    for (int i=0;i<8;i++)
#pragma unroll
        for (int j=0;j<4;j++) acc[i][j]=0.f;

    const int am0 = tid >> 2;          // 0..63
    const int aks = (tid & 3) << 2;    // 0,4,8,12
    const int bn  = tid >> 2;          // 0..63

    for (int k0 = 0; k0 < K; k0 += 16) {
#pragma unroll
        for (int r = 0; r < 2; ++r) {
            int m = am0 + r*64;
            float4 v = *(const float4*)(A + (m0+m)*K + k0 + aks);
            As[aks+0][m]=v.x; As[aks+1][m]=v.y; As[aks+2][m]=v.z; As[aks+3][m]=v.w;
        }
        {
            float4 v = make_float4(0.f,0.f,0.f,0.f);
            if (n0 + bn < N)
                v = *(const float4*)(Bw + (n0+bn)*K + k0 + aks);
            Bs[aks+0][bn]=v.x; Bs[aks+1][bn]=v.y; Bs[aks+2][bn]=v.z; Bs[aks+3][bn]=v.w;
        }
        __syncthreads();
#pragma unroll
        for (int k = 0; k < 16; ++k) {
            float a[8], bb[4];
            float4 a0 = *(const float4*)&As[k][ty*8];
            float4 a1 = *(const float4*)&As[k][ty*8+4];
            float4 b0 = *(const float4*)&Bs[k][tx*4];
            a[0]=a0.x;a[1]=a0.y;a[2]=a0.z;a[3]=a0.w;
            a[4]=a1.x;a[5]=a1.y;a[6]=a1.z;a[7]=a1.w;
            bb[0]=b0.x;bb[1]=b0.y;bb[2]=b0.z;bb[3]=b0.w;
#pragma unroll
            for (int i=0;i<8;i++)
#pragma unroll
                for (int j=0;j<4;j++)
                    acc[i][j] = fmaf(a[i], bb[j], acc[i][j]);
        }
        __syncthreads();
    }
    const int nc = n0 + tx*4;
    if (nc < N) {
#pragma unroll
        for (int i=0;i<8;i++){
            int m = m0 + ty*8 + i;
            float4* cp = (float4*)(C + m*N + nc);
            float4 r;
            r.x=acc[i][0]; r.y=acc[i][1]; r.z=acc[i][2]; r.w=acc[i][3];
            if (ADD) { float4 c=*cp; r.x+=c.x; r.y+=c.y; r.z+=c.z; r.w+=c.w; }
            *cp = r;
        }
    }
}

// ---------------- causal depthwise conv (DC=4) + bias + silu ----------------
__global__ void conv_kernel(const float* __restrict__ xz, const float* __restrict__ cw,
                            const float* __restrict__ cb, float* __restrict__ xcs)
{
    int idx = blockIdx.x*blockDim.x + threadIdx.x;    // over NT*DI
    int d   = idx & (DI_-1);
    int tok = idx >> 9;
    int l   = tok & 1023;
    float4 w = *(const float4*)(cw + d*4);
    float acc = cb[d];
    const float* base = xz + tok*1024 + d;            // xc lives in cols [0,512)
    if (l >= 3) {
        acc += base[-3*1024]*w.x + base[-2*1024]*w.y + base[-1024]*w.z + base[0]*w.w;
    } else {
        float v = base[0]*w.w;
        if (l >= 1) v += base[-1024]*w.z;
        if (l >= 2) v += base[-2*1024]*w.y;
        acc += v;
    }
    float sg = 1.f/(1.f + __expf(-acc));
    xcs[tok*DI_ + d] = acc * sg;
}

// ---------------- dtproj + softplus + B/C split ----------------
__global__ void dtsplit_kernel(const float* __restrict__ xd, const float* __restrict__ dtw,
                               const float* __restrict__ dtb, float* __restrict__ dt,
                               float* __restrict__ Bm, float* __restrict__ Cm)
{
    __shared__ float sx[48];
    int tok = blockIdx.x;
    int j   = threadIdx.x;
    if (j < 48) {
        float v = xd[tok*48 + j];
        sx[j] = v;
        if (j >= 32)      Cm[tok*16 + j-32] = v;
        else if (j >= 16) Bm[tok*16 + j-16] = v;
    }
    __syncthreads();
    float acc = dtb[j];
    const float4* wr = (const float4*)(dtw + j*16);
#pragma unroll
    for (int r4 = 0; r4 < 4; ++r4) {
        float4 w = wr[r4];
        acc += sx[r4*4]*w.x + sx[r4*4+1]*w.y + sx[r4*4+2]*w.z + sx[r4*4+3]*w.w;
    }
    // softplus, stable
    float sp = fmaxf(acc, 0.f) + log1pf(__expf(-fabsf(acc)));
    dt[tok*DI_ + j] = sp;
}

// ---------------- selective scan + D skip + z gating ----------------
// 4 threads per channel (4 states each); 16384 threads total
__global__ void scan_kernel(const float* __restrict__ dt,  const float* __restrict__ xcs,
                            const float* __restrict__ xz,  const float* __restrict__ Bm,
                            const float* __restrict__ Cm,  const float* __restrict__ A_log,
                            const float* __restrict__ D_p, float* __restrict__ ys)
{
    int gtid = blockIdx.x*blockDim.x + threadIdx.x;   // 0..16383
    int s    = gtid & 3;                              // state quad
    int ch   = gtid >> 2;                             // 0..4095
    int b    = ch >> 9;
    int d    = ch & (DI_-1);

    const float* Ap = A_log + d*DS_ + s*4;
    float a0 = -__expf(Ap[0]);
    float a1 = -__expf(Ap[1]);
    float a2 = -__expf(Ap[2]);
    float a3 = -__expf(Ap[3]);
    float Dv = D_p[d];

    float h0=0.f, h1=0.f, h2=0.f, h3=0.f;
    int o512  = b*L_*DI_ + d;
    int o1024 = b*L_*2*DI_ + DI_ + d;
    int o16   = b*L_*DS_ + s*4;

#pragma unroll 2
    for (int t = 0; t < L_; ++t) {
        float dtv = __ldg(dt  + o512);
        float xv  = __ldg(xcs + o512);
        float zv  = __ldg(xz  + o1024);
        float4 B4 = *(const float4*)(Bm + o16);
        float4 C4 = *(const float4*)(Cm + o16);

        float e0 = __expf(dtv*a0);
        float e1 = __expf(dtv*a1);
        float e2 = __expf(dtv*a2);
        float e3 = __expf(dtv*a3);
        float dtx = dtv * xv;
        h0 = fmaf(e0, h0, dtx*B4.x);
        h1 = fmaf(e1, h1, dtx*B4.y);
        h2 = fmaf(e2, h2, dtx*B4.z);
        h3 = fmaf(e3, h3, dtx*B4.w);
        float y = h0*C4.x + h1*C4.y + h2*C4.z + h3*C4.w;
        y += __shfl_xor_sync(0xffffffffu, y, 1);
        y += __shfl_xor_sync(0xffffffffu, y, 2);
        float yt = y + xv*Dv;
        float sg = 1.f/(1.f + __expf(-zv));
        float res = yt * zv * sg;
        if (s == 0) ys[o512] = res;

        o512 += DI_; o1024 += 2*DI_; o16 += DS_;
    }
}

// ---------------- final LN + MLP head (last token only) ----------------
__global__ void final_kernel(const float* __restrict__ h,
                             const float* __restrict__ ng, const float* __restrict__ nb,
                             const float* __restrict__ h1w, const float* __restrict__ h1b,
                             const float* __restrict__ h2w, const float* __restrict__ h2b,
                             const float* __restrict__ stats, float* __restrict__ out)
{
    __shared__ float sl[DM_];
    __shared__ float sf[2*DM_];
    __shared__ float red[40];
    int b = blockIdx.x, tid = threadIdx.x;   // 512 threads
    const float* hr = h + (b*L_ + (L_-1))*DM_;

    float v = (tid < DM_) ? hr[tid] : 0.f;
    float s = v;
#pragma unroll
    for (int o = 16; o; o >>= 1) s += __shfl_xor_sync(0xffffffffu, s, o);
    if ((tid & 31) == 0) red[tid >> 5] = s;
    __syncthreads();
    if (tid == 0) { float t=0; for (int w=0;w<16;w++) t+=red[w]; red[32]=t*(1.f/DM_); }
    __syncthreads();
    float mean = red[32];
    float dv = (tid < DM_) ? (v - mean) : 0.f;
    float q = dv*dv;
#pragma unroll
    for (int o = 16; o; o >>= 1) q += __shfl_xor_sync(0xffffffffu, q, o);
    if ((tid & 31) == 0) red[tid >> 5] = q;
    __syncthreads();
    if (tid == 0) { float t=0; for (int w=0;w<16;w++) t+=red[w]; red[33]=rsqrtf(t*(1.f/DM_)+1e-5f); }
    __syncthreads();
    float rstd = red[33];
    if (tid < DM_) sl[tid] = dv*rstd*ng[tid] + nb[tid];
    __syncthreads();

    // f1 = gelu(last @ h1_w^T + h1_b), 512 outputs
    float acc = h1b[tid];
    const float* wrow = h1w + tid*DM_;
    for (int d2 = 0; d2 < DM_; d2 += 4) {
        float4 w4 = *(const float4*)(wrow + d2);
        acc += sl[d2]*w4.x + sl[d2+1]*w4.y + sl[d2+2]*w4.z + sl[d2+3]*w4.w;
    }
    float g = 0.5f*acc*(1.f + erff(acc*0.70710678118654752f));   // exact gelu
    sf[tid] = g;
    __syncthreads();

    if (tid < MH_) {
        float a2 = h2b[tid];
        const float* w2 = h2w + tid*2*DM_;
        for (int j = 0; j < 2*DM_; j += 4) {
            float4 w4 = *(const float4*)(w2 + j);
            a2 += sf[j]*w4.x + sf[j+1]*w4.y + sf[j+2]*w4.z + sf[j+3]*w4.w;
        }
        out[b*MH_ + tid] = a2 * stats[2*b+1] + stats[2*b];
    }
}

// ---------------- host launcher ----------------
extern "C" void kernel_launch(void* const* d_in, const int* in_sizes, int n_in,
                              void* d_out, int out_size)
{
    const float* x        = (const float*)d_in[0];
    const float* ln_g     = (const float*)d_in[1];
    const float* ln_b     = (const float*)d_in[2];
    const float* in_w     = (const float*)d_in[3];
    const float* conv_w   = (const float*)d_in[4];
    const float* conv_b   = (const float*)d_in[5];
    const float* xproj_w  = (const float*)d_in[6];
    const float* dtproj_w = (const float*)d_in[7];
    const float* dtproj_b = (const float*)d_in[8];
    const float* A_log    = (const float*)d_in[9];
    const float* D_p      = (const float*)d_in[10];
    const float* out_w    = (const float*)d_in[11];
    const float* inp_w    = (const float*)d_in[12];
    const float* inp_b    = (const float*)d_in[13];
    const float* norm_g   = (const float*)d_in[14];
    const float* norm_b   = (const float*)d_in[15];
    const float* h1_w     = (const float*)d_in[16];
    const float* h1_b     = (const float*)d_in[17];
    const float* h2_w     = (const float*)d_in[18];
    const float* h2_b     = (const float*)d_in[19];
    float* out = (float*)d_out;

    float *p_h, *p_u, *p_xz, *p_xcs, *p_xd, *p_dt, *p_B, *p_C, *p_ys, *p_st;
    cudaGetSymbolAddress((void**)&p_h,   g_h);
    cudaGetSymbolAddress((void**)&p_u,   g_u);
    cudaGetSymbolAddress((void**)&p_xz,  g_xz);
    cudaGetSymbolAddress((void**)&p_xcs, g_xcs);
    cudaGetSymbolAddress((void**)&p_xd,  g_xd);
    cudaGetSymbolAddress((void**)&p_dt,  g_dt);
    cudaGetSymbolAddress((void**)&p_B,   g_Bm);
    cudaGetSymbolAddress((void**)&p_C,   g_Cm);
    cudaGetSymbolAddress((void**)&p_ys,  g_ys);
    cudaGetSymbolAddress((void**)&p_st,  g_stats);

    stats_kernel<<<B_, 256>>>(x, p_st);
    embed_kernel<<<NT, DM_>>>(x, inp_w, inp_b, p_st, p_h);

    for (int i = 0; i < NL_; ++i) {
        ln_kernel<<<NT*32/256, 256>>>(p_h, ln_g + i*DM_, ln_b + i*DM_, p_u);
        gemm_tn<false><<<dim3(2*DI_/64, NT/128), 256>>>(p_u, in_w + i*2*DI_*DM_, p_xz, NT, 2*DI_, DM_);
        conv_kernel<<<NT*DI_/256, 256>>>(p_xz, conv_w + i*DI_*4, conv_b + i*DI_, p_xcs);
        gemm_tn<false><<<dim3(1, NT/128), 256>>>(p_xcs, xproj_w + i*48*DI_, p_xd, NT, 48, DI_);
        dtsplit_kernel<<<NT, DI_>>>(p_xd, dtproj_w + i*DI_*DTR_, dtproj_b + i*DI_, p_dt, p_B, p_C);
        scan_kernel<<<128, 128>>>(p_dt, p_xcs, p_xz, p_B, p_C, A_log + i*DI_*DS_, D_p + i*DI_, p_ys);
        gemm_tn<true><<<dim3(DM_/64, NT/128), 256>>>(p_ys, out_w + i*DM_*DI_, p_h, NT, DM_, DI_);
    }

    final_kernel<<<B_, 512>>>(p_h, norm_g, norm_b, h1_w, h1_b, h2_w, h2_b, p_st, out);

    (void)in_sizes; (void)n_in; (void)out_size;
}

// round 5
// speedup vs baseline: 1.7157x; 1.7157x over previous
#include <cuda_runtime.h>
#include <math.h>

// ---------------- problem constants ----------------
#define B_    8
#define L_    1024
#define DM_   256
#define DI_   512
#define DS_   16
#define DTR_  16
#define NL_   4
#define NT    (B_*L_)       // 8192 tokens
#define MH_   96

// ---------------- scratch ----------------
__device__ float g_h   [NT*DM_];
__device__ float g_u   [NT*DM_];
__device__ float g_xz  [NT*2*DI_];
__device__ float g_xcs [NT*DI_];
__device__ float g_xd  [NT*48];
__device__ float g_dt  [NT*DI_];
__device__ float g_Bm  [NT*DS_];
__device__ float g_Cm  [NT*DS_];
__device__ float g_ys  [NT*DI_];
__device__ float g_stats[2*B_];

// ---------------- per-batch mean / std (ddof=1) ----------------
__global__ void stats_kernel(const float* __restrict__ x, float* __restrict__ stats)
{
    __shared__ float sm[256];
    int b = blockIdx.x, tid = threadIdx.x;
    float s = 0.f;
    for (int l = tid; l < L_; l += 256) s += x[b*L_ + l];
    sm[tid] = s; __syncthreads();
    for (int o = 128; o > 0; o >>= 1) { if (tid < o) sm[tid] += sm[tid+o]; __syncthreads(); }
    float mean = sm[0] * (1.f/L_);
    __syncthreads();
    float s2 = 0.f;
    for (int l = tid; l < L_; l += 256) { float d = x[b*L_ + l] - mean; s2 += d*d; }
    sm[tid] = s2; __syncthreads();
    for (int o = 128; o > 0; o >>= 1) { if (tid < o) sm[tid] += sm[tid+o]; __syncthreads(); }
    if (tid == 0) {
        float st = sqrtf(sm[0] / (float)(L_-1));
        st = fmaxf(st, 1e-6f);
        stats[2*b] = mean; stats[2*b+1] = st;
    }
}

// ---------------- input embed + positional encoding ----------------
__global__ void embed_kernel(const float* __restrict__ x, const float* __restrict__ inp_w,
                             const float* __restrict__ inp_b, const float* __restrict__ stats,
                             float* __restrict__ h)
{
    int tok = blockIdx.x;
    int d   = threadIdx.x;
    int b = tok >> 10, l = tok & 1023;
    float xn = (x[tok] - stats[2*b]) / stats[2*b+1];
    float div = expf(-(float)(d & ~1) * (9.2103403719761836f / 256.f));
    float ang = (float)l * div;
    float pe  = (d & 1) ? cosf(ang) : sinf(ang);
    h[tok*DM_ + d] = xn * inp_w[d] + inp_b[d] + pe;
}

// ---------------- per-token layernorm (one warp / token) ----------------
__global__ void ln_kernel(const float* __restrict__ in,
                          const float* __restrict__ gw, const float* __restrict__ bw,
                          float* __restrict__ out)
{
    int gt   = blockIdx.x*blockDim.x + threadIdx.x;
    int tok  = gt >> 5;
    int lane = gt & 31;
    const float4* row = (const float4*)(in + tok*DM_);
    float4 v0 = row[lane];
    float4 v1 = row[lane+32];
    float s = v0.x+v0.y+v0.z+v0.w + v1.x+v1.y+v1.z+v1.w;
#pragma unroll
    for (int o = 16; o; o >>= 1) s += __shfl_xor_sync(0xffffffffu, s, o);
    float mean = s * (1.f/DM_);
    float d0=v0.x-mean, d1=v0.y-mean, d2=v0.z-mean, d3=v0.w-mean;
    float d4=v1.x-mean, d5=v1.y-mean, d6=v1.z-mean, d7=v1.w-mean;
    float q = d0*d0+d1*d1+d2*d2+d3*d3+d4*d4+d5*d5+d6*d6+d7*d7;
#pragma unroll
    for (int o = 16; o; o >>= 1) q += __shfl_xor_sync(0xffffffffu, q, o);
    float rstd = rsqrtf(q * (1.f/DM_) + 1e-5f);
    float4 g0=((const float4*)gw)[lane], g1=((const float4*)gw)[lane+32];
    float4 b0=((const float4*)bw)[lane], b1=((const float4*)bw)[lane+32];
    float4 o0, o1;
    o0.x=d0*rstd*g0.x+b0.x; o0.y=d1*rstd*g0.y+b0.y; o0.z=d2*rstd*g0.z+b0.z; o0.w=d3*rstd*g0.w+b0.w;
    o1.x=d4*rstd*g1.x+b1.x; o1.y=d5*rstd*g1.y+b1.y; o1.z=d6*rstd*g1.z+b1.z; o1.w=d7*rstd*g1.w+b1.w;
    ((float4*)(out + tok*DM_))[lane]    = o0;
    ((float4*)(out + tok*DM_))[lane+32] = o1;
}

// ---------------- double-buffered fp32 GEMM:  C[M,N] (+)= A[M,K] * B[N,K]^T ----------
// 256 threads, tiles BM x BN x 16, per-thread (BM/16)x(BN/16)
template<int BM, int BN, bool ADD>
__global__ void __launch_bounds__(256, 2) gemm_db(
    const float* __restrict__ A, const float* __restrict__ Bw,
    float* __restrict__ C, int M, int N, int K)
{
    constexpr int TM = BM/16, TN = BN/16;
    constexpr int AR = BM/64, BR = BN/64;
    __shared__ float As[2][16][BM];
    __shared__ float Bs[2][16][BN];
    const int tid = threadIdx.x;
    const int m0 = blockIdx.y * BM;
    const int n0 = blockIdx.x * BN;
    const int tx = tid & 15;
    const int ty = tid >> 4;
    const int lr = tid >> 2;          // 0..63
    const int lk = (tid & 3) << 2;    // 0,4,8,12

    float acc[TM][TN];
#pragma unroll
    for (int i=0;i<TM;i++)
#pragma unroll
        for (int j=0;j<TN;j++) acc[i][j]=0.f;

    float4 ra[AR], rb[BR];

    // prologue load chunk 0
#pragma unroll
    for (int r=0;r<AR;r++)
        ra[r] = *(const float4*)(A + (m0 + lr + r*64)*K + lk);
#pragma unroll
    for (int r=0;r<BR;r++) {
        int n = n0 + lr + r*64;
        rb[r] = (n < N) ? *(const float4*)(Bw + n*K + lk) : make_float4(0.f,0.f,0.f,0.f);
    }
#pragma unroll
    for (int r=0;r<AR;r++){
        As[0][lk+0][lr+r*64]=ra[r].x; As[0][lk+1][lr+r*64]=ra[r].y;
        As[0][lk+2][lr+r*64]=ra[r].z; As[0][lk+3][lr+r*64]=ra[r].w;
    }
#pragma unroll
    for (int r=0;r<BR;r++){
        Bs[0][lk+0][lr+r*64]=rb[r].x; Bs[0][lk+1][lr+r*64]=rb[r].y;
        Bs[0][lk+2][lr+r*64]=rb[r].z; Bs[0][lk+3][lr+r*64]=rb[r].w;
    }
    __syncthreads();

    const int nch = K >> 4;
    for (int c = 0; c < nch; ++c) {
        const int p = c & 1;
        if (c+1 < nch) {
            const int k0 = (c+1) << 4;
#pragma unroll
            for (int r=0;r<AR;r++)
                ra[r] = *(const float4*)(A + (m0 + lr + r*64)*K + k0 + lk);
#pragma unroll
            for (int r=0;r<BR;r++) {
                int n = n0 + lr + r*64;
                rb[r] = (n < N) ? *(const float4*)(Bw + n*K + k0 + lk) : make_float4(0.f,0.f,0.f,0.f);
            }
        }
#pragma unroll
        for (int k = 0; k < 16; ++k) {
            float a[TM], bv[TN];
#pragma unroll
            for (int i=0;i<TM/4;i++){
                float4 v = *(const float4*)&As[p][k][ty*TM + i*4];
                a[i*4+0]=v.x; a[i*4+1]=v.y; a[i*4+2]=v.z; a[i*4+3]=v.w;
            }
#pragma unroll
            for (int j=0;j<TN/4;j++){
                float4 v = *(const float4*)&Bs[p][k][tx*TN + j*4];
                bv[j*4+0]=v.x; bv[j*4+1]=v.y; bv[j*4+2]=v.z; bv[j*4+3]=v.w;
            }
#pragma unroll
            for (int i=0;i<TM;i++)
#pragma unroll
                for (int j=0;j<TN;j++)
                    acc[i][j] = fmaf(a[i], bv[j], acc[i][j]);
        }
        if (c+1 < nch) {
            const int q = p ^ 1;
#pragma unroll
            for (int r=0;r<AR;r++){
                As[q][lk+0][lr+r*64]=ra[r].x; As[q][lk+1][lr+r*64]=ra[r].y;
                As[q][lk+2][lr+r*64]=ra[r].z; As[q][lk+3][lr+r*64]=ra[r].w;
            }
#pragma unroll
            for (int r=0;r<BR;r++){
                Bs[q][lk+0][lr+r*64]=rb[r].x; Bs[q][lk+1][lr+r*64]=rb[r].y;
                Bs[q][lk+2][lr+r*64]=rb[r].z; Bs[q][lk+3][lr+r*64]=rb[r].w;
            }
        }
        __syncthreads();
    }

#pragma unroll
    for (int i=0;i<TM;i++){
        int m = m0 + ty*TM + i;
#pragma unroll
        for (int j=0;j<TN/4;j++){
            int n = n0 + tx*TN + j*4;
            if (n < N) {
                float4* cp = (float4*)(C + m*N + n);
                float4 r;
                r.x=acc[i][j*4+0]; r.y=acc[i][j*4+1]; r.z=acc[i][j*4+2]; r.w=acc[i][j*4+3];
                if (ADD) { float4 cc=*cp; r.x+=cc.x; r.y+=cc.y; r.z+=cc.z; r.w+=cc.w; }
                *cp = r;
            }
        }
    }
}

// ---------------- causal depthwise conv (DC=4) + bias + silu ----------------
__global__ void conv_kernel(const float* __restrict__ xz, const float* __restrict__ cw,
                            const float* __restrict__ cb, float* __restrict__ xcs)
{
    int idx = blockIdx.x*blockDim.x + threadIdx.x;
    int d   = idx & (DI_-1);
    int tok = idx >> 9;
    int l   = tok & 1023;
    float4 w = *(const float4*)(cw + d*4);
    float acc = cb[d];
    const float* base = xz + tok*1024 + d;
    if (l >= 3) {
        acc += base[-3*1024]*w.x + base[-2*1024]*w.y + base[-1024]*w.z + base[0]*w.w;
    } else {
        float v = base[0]*w.w;
        if (l >= 1) v += base[-1024]*w.z;
        if (l >= 2) v += base[-2*1024]*w.y;
        acc += v;
    }
    float sg = 1.f/(1.f + __expf(-acc));
    xcs[tok*DI_ + d] = acc * sg;
}

// ---------------- dtproj + softplus + B/C split ----------------
__global__ void dtsplit_kernel(const float* __restrict__ xd, const float* __restrict__ dtw,
                               const float* __restrict__ dtb, float* __restrict__ dt,
                               float* __restrict__ Bm, float* __restrict__ Cm)
{
    __shared__ float sx[48];
    int tok = blockIdx.x;
    int j   = threadIdx.x;
    if (j < 48) {
        float v = xd[tok*48 + j];
        sx[j] = v;
        if (j >= 32)      Cm[tok*16 + j-32] = v;
        else if (j >= 16) Bm[tok*16 + j-16] = v;
    }
    __syncthreads();
    float acc = dtb[j];
    const float4* wr = (const float4*)(dtw + j*16);
#pragma unroll
    for (int r4 = 0; r4 < 4; ++r4) {
        float4 w = wr[r4];
        acc += sx[r4*4]*w.x + sx[r4*4+1]*w.y + sx[r4*4+2]*w.z + sx[r4*4+3]*w.w;
    }
    float sp = fmaxf(acc, 0.f) + log1pf(__expf(-fabsf(acc)));
    dt[tok*DI_ + j] = sp;
}

// ---------------- selective scan, smem-staged + double-buffered time tiles ----------
// block = 128 threads = 32 channels x 4 state-quads; 128 blocks total
#define TT_ 32
__global__ void __launch_bounds__(128) scan_kernel(
    const float* __restrict__ dt,  const float* __restrict__ xcs,
    const float* __restrict__ xz,  const float* __restrict__ Bm,
    const float* __restrict__ Cm,  const float* __restrict__ A_log,
    const float* __restrict__ D_p, float* __restrict__ ys)
{
    __shared__ float s_dt[2][TT_][32];
    __shared__ float s_x [2][TT_][32];
    __shared__ float s_z [2][TT_][32];
    __shared__ float s_B [2][TT_][16];
    __shared__ float s_C [2][TT_][16];

    const int tid = threadIdx.x;
    const int ch0 = blockIdx.x * 32;
    const int b   = ch0 >> 9;
    const int d0  = ch0 & (DI_-1);
    const int s   = tid & 3;
    const int c   = tid >> 2;          // 0..31
    const int d   = d0 + c;

    float4 Av = *(const float4*)(A_log + d*DS_ + s*4);
    const float a0 = -__expf(Av.x);
    const float a1 = -__expf(Av.y);
    const float a2 = -__expf(Av.z);
    const float a3 = -__expf(Av.w);
    const float Dv = D_p[d];

    const float* dt_b = dt  + b*L_*DI_   + d0;
    const float* x_b  = xcs + b*L_*DI_   + d0;
    const float* z_b  = xz  + b*L_*2*DI_ + DI_ + d0;
    const float* B_b  = Bm  + b*L_*DS_;
    const float* C_b  = Cm  + b*L_*DS_;

    // staging lanes
    const int r1   = tid >> 3;         // 0..15 (rows, two passes)
    const int col1 = (tid & 7) << 2;   // 0..28
    const int r2   = tid >> 2;         // 0..31
    const int col2 = (tid & 3) << 2;   // 0..12

    float4 rdt[2], rx[2], rz[2], rB, rC;

    // load tile 0
#pragma unroll
    for (int p=0;p<2;p++){
        int t = r1 + p*16;
        rdt[p] = *(const float4*)(dt_b + t*DI_   + col1);
        rx[p]  = *(const float4*)(x_b  + t*DI_   + col1);
        rz[p]  = *(const float4*)(z_b  + t*2*DI_ + col1);
    }
    rB = *(const float4*)(B_b + r2*DS_ + col2);
    rC = *(const float4*)(C_b + r2*DS_ + col2);
#pragma unroll
    for (int p=0;p<2;p++){
        *(float4*)&s_dt[0][r1+p*16][col1] = rdt[p];
        *(float4*)&s_x [0][r1+p*16][col1] = rx[p];
        *(float4*)&s_z [0][r1+p*16][col1] = rz[p];
    }
    *(float4*)&s_B[0][r2][col2] = rB;
    *(float4*)&s_C[0][r2][col2] = rC;
    __syncthreads();

    float h0=0.f, h1=0.f, h2=0.f, h3=0.f;
    const int ntiles = L_ / TT_;

    for (int tl = 0; tl < ntiles; ++tl) {
        const int q  = tl & 1;
        const int t0 = tl * TT_;
        if (tl+1 < ntiles) {
            const int tn = t0 + TT_;
#pragma unroll
            for (int p=0;p<2;p++){
                int t = tn + r1 + p*16;
                rdt[p] = *(const float4*)(dt_b + t*DI_   + col1);
                rx[p]  = *(const float4*)(x_b  + t*DI_   + col1);
                rz[p]  = *(const float4*)(z_b  + t*2*DI_ + col1);
            }
            rB = *(const float4*)(B_b + (tn+r2)*DS_ + col2);
            rC = *(const float4*)(C_b + (tn+r2)*DS_ + col2);
        }

        float* yo = ys + b*L_*DI_ + t0*DI_ + d;
#pragma unroll 4
        for (int tt = 0; tt < TT_; ++tt) {
            float dtv = s_dt[q][tt][c];
            float xv  = s_x [q][tt][c];
            float zv  = s_z [q][tt][c];
            float4 B4 = *(const float4*)&s_B[q][tt][s*4];
            float4 C4 = *(const float4*)&s_C[q][tt][s*4];

            float e0 = __expf(dtv*a0);
            float e1 = __expf(dtv*a1);
            float e2 = __expf(dtv*a2);
            float e3 = __expf(dtv*a3);
            float dtx = dtv * xv;
            h0 = fmaf(e0, h0, dtx*B4.x);
            h1 = fmaf(e1, h1, dtx*B4.y);
            h2 = fmaf(e2, h2, dtx*B4.z);
            h3 = fmaf(e3, h3, dtx*B4.w);
            float y = h0*C4.x + h1*C4.y + h2*C4.z + h3*C4.w;
            y += __shfl_xor_sync(0xffffffffu, y, 1);
            y += __shfl_xor_sync(0xffffffffu, y, 2);
            float yt  = y + xv*Dv;
            float sg  = 1.f/(1.f + __expf(-zv));
            float res = yt * zv * sg;
            if (s == 0) yo[tt*DI_] = res;
        }

        if (tl+1 < ntiles) {
            const int nq = q ^ 1;
#pragma unroll
            for (int p=0;p<2;p++){
                *(float4*)&s_dt[nq][r1+p*16][col1] = rdt[p];
                *(float4*)&s_x [nq][r1+p*16][col1] = rx[p];
                *(float4*)&s_z [nq][r1+p*16][col1] = rz[p];
            }
            *(float4*)&s_B[nq][r2][col2] = rB;
            *(float4*)&s_C[nq][r2][col2] = rC;
        }
        __syncthreads();
    }
}

// ---------------- final LN + MLP head (last token only) ----------------
__global__ void final_kernel(const float* __restrict__ h,
                             const float* __restrict__ ng, const float* __restrict__ nb,
                             const float* __restrict__ h1w, const float* __restrict__ h1b,
                             const float* __restrict__ h2w, const float* __restrict__ h2b,
                             const float* __restrict__ stats, float* __restrict__ out)
{
    __shared__ float sl[DM_];
    __shared__ float sf[2*DM_];
    __shared__ float red[40];
    int b = blockIdx.x, tid = threadIdx.x;   // 512 threads
    const float* hr = h + (b*L_ + (L_-1))*DM_;

    float v = (tid < DM_) ? hr[tid] : 0.f;
    float s = v;
#pragma unroll
    for (int o = 16; o; o >>= 1) s += __shfl_xor_sync(0xffffffffu, s, o);
    if ((tid & 31) == 0) red[tid >> 5] = s;
    __syncthreads();
    if (tid == 0) { float t=0; for (int w=0;w<16;w++) t+=red[w]; red[32]=t*(1.f/DM_); }
    __syncthreads();
    float mean = red[32];
    float dv = (tid < DM_) ? (v - mean) : 0.f;
    float q = dv*dv;
#pragma unroll
    for (int o = 16; o; o >>= 1) q += __shfl_xor_sync(0xffffffffu, q, o);
    if ((tid & 31) == 0) red[tid >> 5] = q;
    __syncthreads();
    if (tid == 0) { float t=0; for (int w=0;w<16;w++) t+=red[w]; red[33]=rsqrtf(t*(1.f/DM_)+1e-5f); }
    __syncthreads();
    float rstd = red[33];
    if (tid < DM_) sl[tid] = dv*rstd*ng[tid] + nb[tid];
    __syncthreads();

    float acc = h1b[tid];
    const float* wrow = h1w + tid*DM_;
    for (int d2 = 0; d2 < DM_; d2 += 4) {
        float4 w4 = *(const float4*)(wrow + d2);
        acc += sl[d2]*w4.x + sl[d2+1]*w4.y + sl[d2+2]*w4.z + sl[d2+3]*w4.w;
    }
    float g = 0.5f*acc*(1.f + erff(acc*0.70710678118654752f));
    sf[tid] = g;
    __syncthreads();

    if (tid < MH_) {
        float a2 = h2b[tid];
        const float* w2 = h2w + tid*2*DM_;
        for (int j = 0; j < 2*DM_; j += 4) {
            float4 w4 = *(const float4*)(w2 + j);
            a2 += sf[j]*w4.x + sf[j+1]*w4.y + sf[j+2]*w4.z + sf[j+3]*w4.w;
        }
        out[b*MH_ + tid] = a2 * stats[2*b+1] + stats[2*b];
    }
}

// ---------------- host launcher ----------------
extern "C" void kernel_launch(void* const* d_in, const int* in_sizes, int n_in,
                              void* d_out, int out_size)
{
    const float* x        = (const float*)d_in[0];
    const float* ln_g     = (const float*)d_in[1];
    const float* ln_b     = (const float*)d_in[2];
    const float* in_w     = (const float*)d_in[3];
    const float* conv_w   = (const float*)d_in[4];
    const float* conv_b   = (const float*)d_in[5];
    const float* xproj_w  = (const float*)d_in[6];
    const float* dtproj_w = (const float*)d_in[7];
    const float* dtproj_b = (const float*)d_in[8];
    const float* A_log    = (const float*)d_in[9];
    const float* D_p      = (const float*)d_in[10];
    const float* out_w    = (const float*)d_in[11];
    const float* inp_w    = (const float*)d_in[12];
    const float* inp_b    = (const float*)d_in[13];
    const float* norm_g   = (const float*)d_in[14];
    const float* norm_b   = (const float*)d_in[15];
    const float* h1_w     = (const float*)d_in[16];
    const float* h1_b     = (const float*)d_in[17];
    const float* h2_w     = (const float*)d_in[18];
    const float* h2_b     = (const float*)d_in[19];
    float* out = (float*)d_out;

    float *p_h, *p_u, *p_xz, *p_xcs, *p_xd, *p_dt, *p_B, *p_C, *p_ys, *p_st;
    cudaGetSymbolAddress((void**)&p_h,   g_h);
    cudaGetSymbolAddress((void**)&p_u,   g_u);
    cudaGetSymbolAddress((void**)&p_xz,  g_xz);
    cudaGetSymbolAddress((void**)&p_xcs, g_xcs);
    cudaGetSymbolAddress((void**)&p_xd,  g_xd);
    cudaGetSymbolAddress((void**)&p_dt,  g_dt);
    cudaGetSymbolAddress((void**)&p_B,   g_Bm);
    cudaGetSymbolAddress((void**)&p_C,   g_Cm);
    cudaGetSymbolAddress((void**)&p_ys,  g_ys);
    cudaGetSymbolAddress((void**)&p_st,  g_stats);

    stats_kernel<<<B_, 256>>>(x, p_st);
    embed_kernel<<<NT, DM_>>>(x, inp_w, inp_b, p_st, p_h);

    for (int i = 0; i < NL_; ++i) {
        ln_kernel<<<NT*32/256, 256>>>(p_h, ln_g + i*DM_, ln_b + i*DM_, p_u);
        // in_proj: [8192x256] x [1024x256]^T -> [8192x1024]
        gemm_db<128,128,false><<<dim3(2*DI_/128, NT/128), 256>>>(p_u, in_w + i*2*DI_*DM_, p_xz, NT, 2*DI_, DM_);
        conv_kernel<<<NT*DI_/256, 256>>>(p_xz, conv_w + i*DI_*4, conv_b + i*DI_, p_xcs);
        // xproj: [8192x512] x [48x512]^T -> [8192x48]
        gemm_db<64,64,false><<<dim3(1, NT/64), 256>>>(p_xcs, xproj_w + i*48*DI_, p_xd, NT, 48, DI_);
        dtsplit_kernel<<<NT, DI_>>>(p_xd, dtproj_w + i*DI_*DTR_, dtproj_b + i*DI_, p_dt, p_B, p_C);
        scan_kernel<<<128, 128>>>(p_dt, p_xcs, p_xz, p_B, p_C, A_log + i*DI_*DS_, D_p + i*DI_, p_ys);
        // out_proj (accumulate into residual): [8192x512] x [256x512]^T -> += [8192x256]
        gemm_db<64,128,true><<<dim3(DM_/128, NT/64), 256>>>(p_ys, out_w + i*DM_*DI_, p_h, NT, DM_, DI_);
    }

    final_kernel<<<B_, 512>>>(p_h, norm_g, norm_b, h1_w, h1_b, h2_w, h2_b, p_st, out);

    (void)in_sizes; (void)n_in; (void)out_size;
}